// round 10
// baseline (speedup 1.0000x reference)
#include <cuda_runtime.h>
#include <cuda_fp16.h>
#include <cstdint>

#define NUM_USERS  100000
#define NUM_ITEMS  50000
#define N_TOTAL    150100
#define EMBED_DIM  64
#define U4_PER_ROW  8                      // uint4 (8 halves) per half node row
#define U2_PER_ROW  16                     // uint2 (4 halves) per half node row
#define MAX_EDGES  3000000

#define SCAN_T      1024
#define SCAN_CHUNK  4096                   // SCAN_T * 4
#define SCAN_NBLK   37                     // ceil(N_TOTAL / 4096)

// ---------------- device scratch (no runtime allocation) -------------------
__device__ int    g_count  [N_TOTAL];
__device__ int    g_offsets[N_TOTAL];      // block-local exclusive prefix
__device__ int    g_bsum   [SCAN_NBLK];    // per-scan-block exclusive base
__device__ int    g_scan_done;
__device__ int    g_rank   [MAX_EDGES];
__device__ int2   g_pedge  [MAX_EDGES];    // {col, val-bits}, row-grouped
__device__ uint4  g_embh[N_TOTAL * U4_PER_ROW];   // node_emb in half
__device__ uint4  g_l1h [N_TOTAL * U4_PER_ROW];   // layer-1 (half)
__device__ uint4  g_l2h [N_TOTAL * U4_PER_ROW];   // layer-2 (half)

// ---------------------------------------------------------------------------
// Fused: zero g_count + reset scan ticket + convert node_emb fp32 -> fp16.
// ---------------------------------------------------------------------------
__global__ void init_kernel(const float4* __restrict__ emb) {
    int i = blockIdx.x * blockDim.x + threadIdx.x;
    if (i == 0) g_scan_done = 0;
    if (i < N_TOTAL) g_count[i] = 0;
    if (i >= N_TOTAL * U4_PER_ROW) return;
    float4 a = __ldg(emb + 2 * i);
    float4 b = __ldg(emb + 2 * i + 1);
    __half2 h0 = __floats2half2_rn(a.x, a.y);
    __half2 h1 = __floats2half2_rn(a.z, a.w);
    __half2 h2 = __floats2half2_rn(b.x, b.y);
    __half2 h3 = __floats2half2_rn(b.z, b.w);
    uint4 o;
    o.x = *reinterpret_cast<uint32_t*>(&h0);
    o.y = *reinterpret_cast<uint32_t*>(&h1);
    o.z = *reinterpret_cast<uint32_t*>(&h2);
    o.w = *reinterpret_cast<uint32_t*>(&h3);
    g_embh[i] = o;
}

// Histogram; atomic return value = edge's rank within its row. 16 edges/thread.
__global__ void __launch_bounds__(256) hist_kernel(const int* __restrict__ adj_row,
                                                   int n_edges) {
    int i = blockIdx.x * blockDim.x + threadIdx.x;
    int e = i * 16;
    if (e + 15 < n_edges) {
        #pragma unroll
        for (int g = 0; g < 4; g++) {
            int4 r = *(const int4*)(adj_row + e + g * 4);
            int4 k;
            k.x = atomicAdd(&g_count[r.x], 1);
            k.y = atomicAdd(&g_count[r.y], 1);
            k.z = atomicAdd(&g_count[r.z], 1);
            k.w = atomicAdd(&g_count[r.w], 1);
            *(int4*)(g_rank + e + g * 4) = k;
        }
    } else if (e < n_edges) {
        for (int q = e; q < n_edges; q++)
            g_rank[q] = atomicAdd(&g_count[adj_row[q]], 1);
    }
}

// ---------------------------------------------------------------------------
// Single-kernel scan: block-local exclusive scan over a 4096-chunk, then the
// LAST block to finish (atomic ticket) exclusive-scans the 37 block totals.
// ---------------------------------------------------------------------------
__global__ void scan_kernel() {
    __shared__ int wsum[32];
    __shared__ int s_last;
    __shared__ int w0tot;
    int tid  = threadIdx.x;
    int base = blockIdx.x * SCAN_CHUNK;
    int idx  = base + tid * 4;

    int a[4]; int sum = 0;
    #pragma unroll
    for (int k = 0; k < 4; k++) {
        int i = idx + k;
        a[k] = (i < N_TOTAL) ? g_count[i] : 0;
        sum += a[k];
    }
    int v = sum;
    #pragma unroll
    for (int off = 1; off < 32; off <<= 1) {
        int n = __shfl_up_sync(0xffffffffu, v, off);
        if ((tid & 31) >= off) v += n;
    }
    if ((tid & 31) == 31) wsum[tid >> 5] = v;
    __syncthreads();
    if (tid < 32) {
        int w = wsum[tid];
        #pragma unroll
        for (int off = 1; off < 32; off <<= 1) {
            int n = __shfl_up_sync(0xffffffffu, w, off);
            if (tid >= off) w += n;
        }
        wsum[tid] = w;
    }
    __syncthreads();
    int incl = v + ((tid >= 32) ? wsum[(tid >> 5) - 1] : 0);
    int run  = incl - sum;                 // block-local exclusive base
    #pragma unroll
    for (int k = 0; k < 4; k++) {
        int i = idx + k;
        if (i < N_TOTAL) g_offsets[i] = run;
        run += a[k];
    }

    // publish block total, take a ticket
    if (tid == 0) {
        g_bsum[blockIdx.x] = wsum[31];
        __threadfence();
        int ticket = atomicAdd(&g_scan_done, 1);
        s_last = (ticket == SCAN_NBLK - 1);
    }
    __syncthreads();

    // last block: exclusive scan of the 37 block totals
    if (s_last) {
        __threadfence();
        int bv = 0, x = 0;
        if (tid < 64) {
            bv = (tid < SCAN_NBLK) ? g_bsum[tid] : 0;
            x = bv;
            #pragma unroll
            for (int off = 1; off < 32; off <<= 1) {
                int n = __shfl_up_sync(0xffffffffu, x, off);
                if ((tid & 31) >= off) x += n;
            }
        }
        if (tid == 31) w0tot = x;
        __syncthreads();
        if (tid >= 32 && tid < 64) x += w0tot;
        if (tid < SCAN_NBLK) g_bsum[tid] = x - bv;
    }
}

__device__ __forceinline__ int row_base(int r) {
    return __ldg(&g_offsets[r]) + __ldg(&g_bsum[r >> 12]);
}

// Atomic-free permute: p = base(row) + rank[e]. 16 edges/thread.
__global__ void __launch_bounds__(256) fill_kernel(const int* __restrict__ adj_row,
                                                   const int* __restrict__ adj_col,
                                                   const float* __restrict__ adj_val,
                                                   int n_edges) {
    int i = blockIdx.x * blockDim.x + threadIdx.x;
    int e = i * 16;
    if (e + 15 < n_edges) {
        #pragma unroll
        for (int g = 0; g < 4; g++) {
            int4   r = *(const int4*)(adj_row + e + g * 4);
            int4   k = *(const int4*)(g_rank  + e + g * 4);
            int4   c = *(const int4*)(adj_col + e + g * 4);
            float4 v = *(const float4*)(adj_val + e + g * 4);
            g_pedge[row_base(r.x) + k.x] = make_int2(c.x, __float_as_int(v.x));
            g_pedge[row_base(r.y) + k.y] = make_int2(c.y, __float_as_int(v.y));
            g_pedge[row_base(r.z) + k.z] = make_int2(c.z, __float_as_int(v.z));
            g_pedge[row_base(r.w) + k.w] = make_int2(c.w, __float_as_int(v.w));
        }
    } else if (e < n_edges) {
        for (int q = e; q < n_edges; q++)
            g_pedge[row_base(adj_row[q]) + g_rank[q]] =
                make_int2(adj_col[q], __float_as_int(adj_val[q]));
    }
}

// ---------------------------------------------------------------------------
// CSR SpMM, warp-per-row: 4 edge-slots x 8 lanes; each lane owns one uint4
// (8 halves). Unroll x2 -> 8 gathers in flight per warp. Epilogue: shfl_xor
// tree-sum across edge-slots, lanes 0-7 write the row. No intra-warp row
// imbalance.
// ---------------------------------------------------------------------------
__device__ __forceinline__ void fma_h8(float2 acc[4], uint4 x, float v) {
    const __half2* h = reinterpret_cast<const __half2*>(&x);
    #pragma unroll
    for (int k = 0; k < 4; k++) {
        float2 f = __half22float2(h[k]);
        acc[k].x += v * f.x;
        acc[k].y += v * f.y;
    }
}

__global__ void __launch_bounds__(256) spmm_half_kernel(const uint4* __restrict__ in,
                                                        uint4* __restrict__ out) {
    int t    = blockIdx.x * blockDim.x + threadIdx.x;
    int r    = t >> 5;                      // warp id == row
    int lane = t & 31;
    if (r >= N_TOTAL) return;

    int sub = lane >> 3;                    // edge slot 0..3
    int sl  = lane & 7;                     // uint4 slot within row

    int beg = row_base(r);
    int cnt = __ldg(&g_count[r]);
    int end = beg + cnt;

    float2 acc[4];
    #pragma unroll
    for (int k = 0; k < 4; k++) acc[k] = make_float2(0.f, 0.f);

    int j = beg + sub;
    // unroll x2: two edges per lane-iteration, 8 edges per warp-iteration
    for (; j + 4 < end; j += 8) {
        int2 e0 = __ldg(&g_pedge[j]);
        int2 e1 = __ldg(&g_pedge[j + 4]);
        uint4 x0 = __ldg(in + (long long)e0.x * U4_PER_ROW + sl);
        uint4 x1 = __ldg(in + (long long)e1.x * U4_PER_ROW + sl);
        fma_h8(acc, x0, __int_as_float(e0.y));
        fma_h8(acc, x1, __int_as_float(e1.y));
    }
    if (j < end) {
        int2 e0 = __ldg(&g_pedge[j]);
        uint4 x0 = __ldg(in + (long long)e0.x * U4_PER_ROW + sl);
        fma_h8(acc, x0, __int_as_float(e0.y));
    }

    // sum the 4 edge-slot partials (lanes sl, sl+8, sl+16, sl+24)
    #pragma unroll
    for (int k = 0; k < 4; k++) {
        acc[k].x += __shfl_xor_sync(0xffffffffu, acc[k].x, 8);
        acc[k].y += __shfl_xor_sync(0xffffffffu, acc[k].y, 8);
        acc[k].x += __shfl_xor_sync(0xffffffffu, acc[k].x, 16);
        acc[k].y += __shfl_xor_sync(0xffffffffu, acc[k].y, 16);
    }

    if (sub == 0) {
        __half2 o0 = __floats2half2_rn(acc[0].x, acc[0].y);
        __half2 o1 = __floats2half2_rn(acc[1].x, acc[1].y);
        __half2 o2 = __floats2half2_rn(acc[2].x, acc[2].y);
        __half2 o3 = __floats2half2_rn(acc[3].x, acc[3].y);
        uint4 o;
        o.x = *reinterpret_cast<uint32_t*>(&o0);
        o.y = *reinterpret_cast<uint32_t*>(&o1);
        o.z = *reinterpret_cast<uint32_t*>(&o2);
        o.w = *reinterpret_cast<uint32_t*>(&o3);
        out[(long long)r * U4_PER_ROW + sl] = o;
    }
}

// ---------------------------------------------------------------------------
// Fused layer-3 + accumulate + dot at the sampled rows.
// One warp per pair: lanes 0-15 user row, lanes 16-31 item row.
// ---------------------------------------------------------------------------
__global__ void final_kernel(const float4* __restrict__ emb,
                             const int* __restrict__ user_ids,
                             const int* __restrict__ item_ids,
                             float* __restrict__ out,
                             int n_pairs) {
    int t    = blockIdx.x * blockDim.x + threadIdx.x;
    int p    = t >> 5;
    int lane = t & 31;
    if (p >= n_pairs) return;

    int half_ = lane >> 4;                  // 0 = user, 1 = item
    int sl    = lane & 15;
    int row   = half_ ? (NUM_USERS + __ldg(item_ids + p)) : __ldg(user_ids + p);

    const uint2* l1u = reinterpret_cast<const uint2*>(g_l1h);
    const uint2* l2u = reinterpret_cast<const uint2*>(g_l2h);

    long long off = (long long)row * U2_PER_ROW + sl;
    float4 e4 = __ldg(emb + off);

    uint2 u1 = __ldg(l1u + off);
    uint2 u2 = __ldg(l2u + off);
    const __half2* h1 = reinterpret_cast<const __half2*>(&u1);
    const __half2* h2 = reinterpret_cast<const __half2*>(&u2);
    float2 a0 = __half22float2(h1[0]), a1 = __half22float2(h1[1]);
    float2 b0 = __half22float2(h2[0]), b1 = __half22float2(h2[1]);

    float4 acc = make_float4(e4.x + a0.x + b0.x,
                             e4.y + a0.y + b0.y,
                             e4.z + a1.x + b1.x,
                             e4.w + a1.y + b1.y);

    // layer-3 gather (from l2 half) for this row
    int beg = row_base(row);
    int cnt = __ldg(&g_count[row]);
    float4 l3 = make_float4(0.f, 0.f, 0.f, 0.f);
    int j = 0;
    for (; j + 1 < cnt; j += 2) {
        int2 ed0 = __ldg(&g_pedge[beg + j]);
        int2 ed1 = __ldg(&g_pedge[beg + j + 1]);
        uint2 x0 = __ldg(l2u + (long long)ed0.x * U2_PER_ROW + sl);
        uint2 x1 = __ldg(l2u + (long long)ed1.x * U2_PER_ROW + sl);
        float v0 = __int_as_float(ed0.y), v1 = __int_as_float(ed1.y);
        const __half2* p0 = reinterpret_cast<const __half2*>(&x0);
        const __half2* p1 = reinterpret_cast<const __half2*>(&x1);
        float2 f00 = __half22float2(p0[0]), f01 = __half22float2(p0[1]);
        float2 f10 = __half22float2(p1[0]), f11 = __half22float2(p1[1]);
        l3.x += v0 * f00.x + v1 * f10.x;
        l3.y += v0 * f00.y + v1 * f10.y;
        l3.z += v0 * f01.x + v1 * f11.x;
        l3.w += v0 * f01.y + v1 * f11.y;
    }
    if (j < cnt) {
        int2 ed0 = __ldg(&g_pedge[beg + j]);
        uint2 x0 = __ldg(l2u + (long long)ed0.x * U2_PER_ROW + sl);
        float v0 = __int_as_float(ed0.y);
        const __half2* p0 = reinterpret_cast<const __half2*>(&x0);
        float2 f00 = __half22float2(p0[0]), f01 = __half22float2(p0[1]);
        l3.x += v0 * f00.x; l3.y += v0 * f00.y;
        l3.z += v0 * f01.x; l3.w += v0 * f01.y;
    }

    acc.x = (acc.x + l3.x) * 0.25f;
    acc.y = (acc.y + l3.y) * 0.25f;
    acc.z = (acc.z + l3.z) * 0.25f;
    acc.w = (acc.w + l3.w) * 0.25f;

    float4 oth;
    oth.x = __shfl_xor_sync(0xffffffffu, acc.x, 16);
    oth.y = __shfl_xor_sync(0xffffffffu, acc.y, 16);
    oth.z = __shfl_xor_sync(0xffffffffu, acc.z, 16);
    oth.w = __shfl_xor_sync(0xffffffffu, acc.w, 16);

    float partial = acc.x*oth.x + acc.y*oth.y + acc.z*oth.z + acc.w*oth.w;

    #pragma unroll
    for (int o = 8; o > 0; o >>= 1)
        partial += __shfl_down_sync(0xffffffffu, partial, o);

    if (lane == 0) out[p] = partial;
}

// ---------------------------------------------------------------------------
extern "C" void kernel_launch(void* const* d_in, const int* in_sizes, int n_in,
                              void* d_out, int out_size) {
    const float4* node_emb = (const float4*)d_in[0];
    const float*  adj_val  = (const float*)d_in[1];
    const int*    adj_row  = (const int*)d_in[2];
    const int*    adj_col  = (const int*)d_in[3];
    const int*    user_ids = (const int*)d_in[4];
    const int*    item_ids = (const int*)d_in[5];
    float*        out      = (float*)d_out;

    int n_edges = in_sizes[1];
    int n_pairs = out_size;

    uint4 *embh, *l1h, *l2h;
    cudaGetSymbolAddress((void**)&embh, g_embh);
    cudaGetSymbolAddress((void**)&l1h,  g_l1h);
    cudaGetSymbolAddress((void**)&l2h,  g_l2h);

    const int TB = 256;
    int init_blocks   = (N_TOTAL * U4_PER_ROW + TB - 1) / TB;
    int edge16_blocks = ((n_edges + 15) / 16 + TB - 1) / TB;
    int rowwarp_blocks = ((long long)N_TOTAL * 32 + TB - 1) / TB;
    int pair_blocks   = (n_pairs * 32 + TB - 1) / TB;

    // --- CSR build + half conversion ---
    init_kernel<<<init_blocks, TB>>>(node_emb);
    hist_kernel<<<edge16_blocks, TB>>>(adj_row, n_edges);
    scan_kernel<<<SCAN_NBLK, SCAN_T>>>();
    fill_kernel<<<edge16_blocks, TB>>>(adj_row, adj_col, adj_val, n_edges);

    // --- 2 full propagation layers in half (warp-per-row) ---
    spmm_half_kernel<<<rowwarp_blocks, TB>>>(embh, l1h);    // l1
    spmm_half_kernel<<<rowwarp_blocks, TB>>>(l1h,  l2h);    // l2

    // --- fused l3 + acc + dot at the sampled rows only ---
    final_kernel<<<pair_blocks, TB>>>(node_emb, user_ids, item_ids, out, n_pairs);
}

// round 12
// speedup vs baseline: 1.2350x; 1.2350x over previous
#include <cuda_runtime.h>
#include <cuda_fp16.h>
#include <cstdint>

#define NUM_USERS  100000
#define NUM_ITEMS  50000
#define N_TOTAL    150100
#define EMBED_DIM  64
#define U4_PER_ROW  8                      // uint4 (8 halves) per half node row
#define U2_PER_ROW  16                     // uint2 (4 halves) per half node row
#define MAX_EDGES  3000000

#define SCAN_T      1024
#define SCAN_CHUNK  4096                   // SCAN_T * 4
#define SCAN_NBLK   37                     // ceil(N_TOTAL / 4096)

// ---------------- device scratch (no runtime allocation) -------------------
__device__ int    g_count  [N_TOTAL];
__device__ int    g_offsets[N_TOTAL];      // block-local exclusive prefix
__device__ int    g_bsum   [SCAN_NBLK];    // per-scan-block exclusive base
__device__ int    g_scan_done;
__device__ int    g_rank   [MAX_EDGES];
__device__ int2   g_pedge  [MAX_EDGES];    // {col, val-bits}, row-grouped
__device__ uint4  g_embh[N_TOTAL * U4_PER_ROW];   // node_emb in half
__device__ uint4  g_l1h [N_TOTAL * U4_PER_ROW];   // layer-1 (half)
__device__ uint4  g_l2h [N_TOTAL * U4_PER_ROW];   // layer-2 (half)

// ---------------------------------------------------------------------------
// Zero counters + scan ticket (tiny).
// ---------------------------------------------------------------------------
__global__ void zero_kernel() {
    int i = blockIdx.x * blockDim.x + threadIdx.x;
    if (i == 0) g_scan_done = 0;
    if (i < N_TOTAL) g_count[i] = 0;
}

// Histogram; atomic return value = edge's rank within its row. 8 edges/thread.
__global__ void __launch_bounds__(256) hist_kernel(const int* __restrict__ adj_row,
                                                   int n_edges) {
    int i = blockIdx.x * blockDim.x + threadIdx.x;
    int e = i * 8;
    if (e + 7 < n_edges) {
        #pragma unroll
        for (int g = 0; g < 2; g++) {
            int4 r = *(const int4*)(adj_row + e + g * 4);
            int4 k;
            k.x = atomicAdd(&g_count[r.x], 1);
            k.y = atomicAdd(&g_count[r.y], 1);
            k.z = atomicAdd(&g_count[r.z], 1);
            k.w = atomicAdd(&g_count[r.w], 1);
            *(int4*)(g_rank + e + g * 4) = k;
        }
    } else if (e < n_edges) {
        for (int q = e; q < n_edges; q++)
            g_rank[q] = atomicAdd(&g_count[adj_row[q]], 1);
    }
}

// ---------------------------------------------------------------------------
// Single-kernel scan: block-local exclusive scan over a 4096-chunk; last block
// (atomic ticket) exclusive-scans the 37 block totals.
// ---------------------------------------------------------------------------
__global__ void scan_kernel() {
    __shared__ int wsum[32];
    __shared__ int s_last;
    __shared__ int w0tot;
    int tid  = threadIdx.x;
    int base = blockIdx.x * SCAN_CHUNK;
    int idx  = base + tid * 4;

    int a[4]; int sum = 0;
    #pragma unroll
    for (int k = 0; k < 4; k++) {
        int i = idx + k;
        a[k] = (i < N_TOTAL) ? g_count[i] : 0;
        sum += a[k];
    }
    int v = sum;
    #pragma unroll
    for (int off = 1; off < 32; off <<= 1) {
        int n = __shfl_up_sync(0xffffffffu, v, off);
        if ((tid & 31) >= off) v += n;
    }
    if ((tid & 31) == 31) wsum[tid >> 5] = v;
    __syncthreads();
    if (tid < 32) {
        int w = wsum[tid];
        #pragma unroll
        for (int off = 1; off < 32; off <<= 1) {
            int n = __shfl_up_sync(0xffffffffu, w, off);
            if (tid >= off) w += n;
        }
        wsum[tid] = w;
    }
    __syncthreads();
    int incl = v + ((tid >= 32) ? wsum[(tid >> 5) - 1] : 0);
    int run  = incl - sum;
    #pragma unroll
    for (int k = 0; k < 4; k++) {
        int i = idx + k;
        if (i < N_TOTAL) g_offsets[i] = run;
        run += a[k];
    }

    if (tid == 0) {
        g_bsum[blockIdx.x] = wsum[31];
        __threadfence();
        int ticket = atomicAdd(&g_scan_done, 1);
        s_last = (ticket == SCAN_NBLK - 1);
    }
    __syncthreads();

    if (s_last) {
        __threadfence();
        int bv = 0, x = 0;
        if (tid < 64) {
            bv = (tid < SCAN_NBLK) ? g_bsum[tid] : 0;
            x = bv;
            #pragma unroll
            for (int off = 1; off < 32; off <<= 1) {
                int n = __shfl_up_sync(0xffffffffu, x, off);
                if ((tid & 31) >= off) x += n;
            }
        }
        if (tid == 31) w0tot = x;
        __syncthreads();
        if (tid >= 32 && tid < 64) x += w0tot;
        if (tid < SCAN_NBLK) g_bsum[tid] = x - bv;
    }
}

__device__ __forceinline__ int row_base(int r) {
    return __ldg(&g_offsets[r]) + __ldg(&g_bsum[r >> 12]);
}

// ---------------------------------------------------------------------------
// fill: atomic-free permute (4 edges/thread) + fused fp32->fp16 conversion
// (grid-stride, coalesced — overlaps with the scatter's LSU issue stalls).
// ---------------------------------------------------------------------------
__global__ void __launch_bounds__(256) fill_kernel(const int* __restrict__ adj_row,
                                                   const int* __restrict__ adj_col,
                                                   const float* __restrict__ adj_val,
                                                   const float4* __restrict__ emb,
                                                   int n_edges) {
    int i = blockIdx.x * blockDim.x + threadIdx.x;
    int nthreads = gridDim.x * blockDim.x;

    // fused conversion: node_emb fp32 -> fp16 (coalesced)
    for (int c = i; c < N_TOTAL * U4_PER_ROW; c += nthreads) {
        float4 a = __ldg(emb + 2 * c);
        float4 b = __ldg(emb + 2 * c + 1);
        __half2 h0 = __floats2half2_rn(a.x, a.y);
        __half2 h1 = __floats2half2_rn(a.z, a.w);
        __half2 h2 = __floats2half2_rn(b.x, b.y);
        __half2 h3 = __floats2half2_rn(b.z, b.w);
        uint4 o;
        o.x = *reinterpret_cast<uint32_t*>(&h0);
        o.y = *reinterpret_cast<uint32_t*>(&h1);
        o.z = *reinterpret_cast<uint32_t*>(&h2);
        o.w = *reinterpret_cast<uint32_t*>(&h3);
        g_embh[c] = o;
    }

    // edge permute, 4 edges/thread
    int e = i * 4;
    if (e + 3 < n_edges) {
        int4   r = *(const int4*)(adj_row + e);
        int4   k = *(const int4*)(g_rank  + e);
        int4   c = *(const int4*)(adj_col + e);
        float4 v = *(const float4*)(adj_val + e);
        g_pedge[row_base(r.x) + k.x] = make_int2(c.x, __float_as_int(v.x));
        g_pedge[row_base(r.y) + k.y] = make_int2(c.y, __float_as_int(v.y));
        g_pedge[row_base(r.z) + k.z] = make_int2(c.z, __float_as_int(v.z));
        g_pedge[row_base(r.w) + k.w] = make_int2(c.w, __float_as_int(v.w));
    } else if (e < n_edges) {
        for (int q = e; q < n_edges; q++)
            g_pedge[row_base(adj_row[q]) + g_rank[q]] =
                make_int2(adj_col[q], __float_as_int(adj_val[q]));
    }
}

// ---------------------------------------------------------------------------
// CSR SpMM in half: 8 lanes/row, lane owns 8 halves (uint4 = 16B).
// Software-pipelined: next 4 edge records load while current 4 gathers fly.
// fp32 accumulation, half output. (R9 version — proven fastest.)
// ---------------------------------------------------------------------------
__device__ __forceinline__ void fma_h8(float2 acc[4], uint4 x, float v) {
    const __half2* h = reinterpret_cast<const __half2*>(&x);
    #pragma unroll
    for (int k = 0; k < 4; k++) {
        float2 f = __half22float2(h[k]);
        acc[k].x += v * f.x;
        acc[k].y += v * f.y;
    }
}

__global__ void __launch_bounds__(256) spmm_half_kernel(const uint4* __restrict__ in,
                                                        uint4* __restrict__ out) {
    int t    = blockIdx.x * blockDim.x + threadIdx.x;
    int r    = t >> 3;
    int lane = t & 7;
    if (r >= N_TOTAL) return;

    int beg = row_base(r);
    int cnt = __ldg(&g_count[r]);

    float2 acc[4];
    #pragma unroll
    for (int k = 0; k < 4; k++) acc[k] = make_float2(0.f, 0.f);

    int j = 0;
    int2 ea0, ea1, ea2, ea3;
    if (j + 3 < cnt) {
        ea0 = __ldg(&g_pedge[beg]);
        ea1 = __ldg(&g_pedge[beg + 1]);
        ea2 = __ldg(&g_pedge[beg + 2]);
        ea3 = __ldg(&g_pedge[beg + 3]);
    }
    while (j + 3 < cnt) {
        uint4 x0 = __ldg(in + (long long)ea0.x * U4_PER_ROW + lane);
        uint4 x1 = __ldg(in + (long long)ea1.x * U4_PER_ROW + lane);
        uint4 x2 = __ldg(in + (long long)ea2.x * U4_PER_ROW + lane);
        uint4 x3 = __ldg(in + (long long)ea3.x * U4_PER_ROW + lane);
        int jn = j + 4;
        int2 eb0, eb1, eb2, eb3;
        bool more = (jn + 3 < cnt);
        if (more) {
            eb0 = __ldg(&g_pedge[beg + jn]);
            eb1 = __ldg(&g_pedge[beg + jn + 1]);
            eb2 = __ldg(&g_pedge[beg + jn + 2]);
            eb3 = __ldg(&g_pedge[beg + jn + 3]);
        }
        fma_h8(acc, x0, __int_as_float(ea0.y));
        fma_h8(acc, x1, __int_as_float(ea1.y));
        fma_h8(acc, x2, __int_as_float(ea2.y));
        fma_h8(acc, x3, __int_as_float(ea3.y));
        ea0 = eb0; ea1 = eb1; ea2 = eb2; ea3 = eb3;
        j = jn;
    }
    for (; j < cnt; j++) {
        int2 e0 = __ldg(&g_pedge[beg + j]);
        uint4 x0 = __ldg(in + (long long)e0.x * U4_PER_ROW + lane);
        fma_h8(acc, x0, __int_as_float(e0.y));
    }

    __half2 o0 = __floats2half2_rn(acc[0].x, acc[0].y);
    __half2 o1 = __floats2half2_rn(acc[1].x, acc[1].y);
    __half2 o2 = __floats2half2_rn(acc[2].x, acc[2].y);
    __half2 o3 = __floats2half2_rn(acc[3].x, acc[3].y);
    uint4 o;
    o.x = *reinterpret_cast<uint32_t*>(&o0);
    o.y = *reinterpret_cast<uint32_t*>(&o1);
    o.z = *reinterpret_cast<uint32_t*>(&o2);
    o.w = *reinterpret_cast<uint32_t*>(&o3);
    out[(long long)r * U4_PER_ROW + lane] = o;
}

// ---------------------------------------------------------------------------
// Fused layer-3 + accumulate + dot at the sampled rows.
// One warp per pair: lanes 0-15 user row, lanes 16-31 item row.
// ---------------------------------------------------------------------------
__global__ void final_kernel(const float4* __restrict__ emb,
                             const int* __restrict__ user_ids,
                             const int* __restrict__ item_ids,
                             float* __restrict__ out,
                             int n_pairs) {
    int t    = blockIdx.x * blockDim.x + threadIdx.x;
    int p    = t >> 5;
    int lane = t & 31;
    if (p >= n_pairs) return;

    int half_ = lane >> 4;                  // 0 = user, 1 = item
    int sl    = lane & 15;
    int row   = half_ ? (NUM_USERS + __ldg(item_ids + p)) : __ldg(user_ids + p);

    const uint2* l1u = reinterpret_cast<const uint2*>(g_l1h);
    const uint2* l2u = reinterpret_cast<const uint2*>(g_l2h);

    long long off = (long long)row * U2_PER_ROW + sl;
    float4 e4 = __ldg(emb + off);

    uint2 u1 = __ldg(l1u + off);
    uint2 u2 = __ldg(l2u + off);
    const __half2* h1 = reinterpret_cast<const __half2*>(&u1);
    const __half2* h2 = reinterpret_cast<const __half2*>(&u2);
    float2 a0 = __half22float2(h1[0]), a1 = __half22float2(h1[1]);
    float2 b0 = __half22float2(h2[0]), b1 = __half22float2(h2[1]);

    float4 acc = make_float4(e4.x + a0.x + b0.x,
                             e4.y + a0.y + b0.y,
                             e4.z + a1.x + b1.x,
                             e4.w + a1.y + b1.y);

    int beg = row_base(row);
    int cnt = __ldg(&g_count[row]);
    float4 l3 = make_float4(0.f, 0.f, 0.f, 0.f);
    int j = 0;
    for (; j + 1 < cnt; j += 2) {
        int2 ed0 = __ldg(&g_pedge[beg + j]);
        int2 ed1 = __ldg(&g_pedge[beg + j + 1]);
        uint2 x0 = __ldg(l2u + (long long)ed0.x * U2_PER_ROW + sl);
        uint2 x1 = __ldg(l2u + (long long)ed1.x * U2_PER_ROW + sl);
        float v0 = __int_as_float(ed0.y), v1 = __int_as_float(ed1.y);
        const __half2* p0 = reinterpret_cast<const __half2*>(&x0);
        const __half2* p1 = reinterpret_cast<const __half2*>(&x1);
        float2 f00 = __half22float2(p0[0]), f01 = __half22float2(p0[1]);
        float2 f10 = __half22float2(p1[0]), f11 = __half22float2(p1[1]);
        l3.x += v0 * f00.x + v1 * f10.x;
        l3.y += v0 * f00.y + v1 * f10.y;
        l3.z += v0 * f01.x + v1 * f11.x;
        l3.w += v0 * f01.y + v1 * f11.y;
    }
    if (j < cnt) {
        int2 ed0 = __ldg(&g_pedge[beg + j]);
        uint2 x0 = __ldg(l2u + (long long)ed0.x * U2_PER_ROW + sl);
        float v0 = __int_as_float(ed0.y);
        const __half2* p0 = reinterpret_cast<const __half2*>(&x0);
        float2 f00 = __half22float2(p0[0]), f01 = __half22float2(p0[1]);
        l3.x += v0 * f00.x; l3.y += v0 * f00.y;
        l3.z += v0 * f01.x; l3.w += v0 * f01.y;
    }

    acc.x = (acc.x + l3.x) * 0.25f;
    acc.y = (acc.y + l3.y) * 0.25f;
    acc.z = (acc.z + l3.z) * 0.25f;
    acc.w = (acc.w + l3.w) * 0.25f;

    float4 oth;
    oth.x = __shfl_xor_sync(0xffffffffu, acc.x, 16);
    oth.y = __shfl_xor_sync(0xffffffffu, acc.y, 16);
    oth.z = __shfl_xor_sync(0xffffffffu, acc.z, 16);
    oth.w = __shfl_xor_sync(0xffffffffu, acc.w, 16);

    float partial = acc.x*oth.x + acc.y*oth.y + acc.z*oth.z + acc.w*oth.w;

    #pragma unroll
    for (int o = 8; o > 0; o >>= 1)
        partial += __shfl_down_sync(0xffffffffu, partial, o);

    if (lane == 0) out[p] = partial;
}

// ---------------------------------------------------------------------------
extern "C" void kernel_launch(void* const* d_in, const int* in_sizes, int n_in,
                              void* d_out, int out_size) {
    const float4* node_emb = (const float4*)d_in[0];
    const float*  adj_val  = (const float*)d_in[1];
    const int*    adj_row  = (const int*)d_in[2];
    const int*    adj_col  = (const int*)d_in[3];
    const int*    user_ids = (const int*)d_in[4];
    const int*    item_ids = (const int*)d_in[5];
    float*        out      = (float*)d_out;

    int n_edges = in_sizes[1];
    int n_pairs = out_size;

    uint4 *embh, *l1h, *l2h;
    cudaGetSymbolAddress((void**)&embh, g_embh);
    cudaGetSymbolAddress((void**)&l1h,  g_l1h);
    cudaGetSymbolAddress((void**)&l2h,  g_l2h);

    const int TB = 256;
    int zero_blocks   = (N_TOTAL + TB - 1) / TB;
    int edge8_blocks  = ((n_edges + 7) / 8 + TB - 1) / TB;
    int edge4_blocks  = ((n_edges + 3) / 4 + TB - 1) / TB;
    int row_blocks    = (N_TOTAL * 8 + TB - 1) / TB;
    int pair_blocks   = (n_pairs * 32 + TB - 1) / TB;

    // --- CSR build + fused fp16 conversion ---
    zero_kernel<<<zero_blocks, TB>>>();
    hist_kernel<<<edge8_blocks, TB>>>(adj_row, n_edges);
    scan_kernel<<<SCAN_NBLK, SCAN_T>>>();
    fill_kernel<<<edge4_blocks, TB>>>(adj_row, adj_col, adj_val, node_emb, n_edges);

    // --- 2 full propagation layers in half (8-lane pipelined) ---
    spmm_half_kernel<<<row_blocks, TB>>>(embh, l1h);    // l1
    spmm_half_kernel<<<row_blocks, TB>>>(l1h,  l2h);    // l2

    // --- fused l3 + acc + dot at the sampled rows only ---
    final_kernel<<<pair_blocks, TB>>>(node_emb, user_ids, item_ids, out, n_pairs);
}

// round 14
// speedup vs baseline: 1.2629x; 1.0226x over previous
#include <cuda_runtime.h>
#include <cuda_fp16.h>
#include <cstdint>

#define NUM_USERS  100000
#define NUM_ITEMS  50000
#define N_TOTAL    150100
#define EMBED_DIM  64
#define U4_PER_ROW  8                      // uint4 (8 halves) per half node row
#define U2_PER_ROW  16                     // uint2 (4 halves) per half node row
#define MAX_EDGES  3000000

#define SCAN_T      1024
#define SCAN_CHUNK  4096                   // SCAN_T * 4
#define SCAN_NBLK   37                     // ceil(N_TOTAL / 4096)

// ---------------- device scratch (no runtime allocation) -------------------
__device__ int    g_count  [N_TOTAL];
__device__ int    g_offsets[N_TOTAL];      // exclusive prefix (final, absolute)
__device__ int    g_cursor [N_TOTAL];      // running copy for fill
__device__ int    g_bsum   [SCAN_NBLK];
__device__ int    g_scan_done;
__device__ int2   g_pedge  [MAX_EDGES];    // {col, val-bits}, row-grouped
__device__ uint4  g_embh[N_TOTAL * U4_PER_ROW];   // node_emb in half
__device__ uint4  g_l1h [N_TOTAL * U4_PER_ROW];   // layer-1 (half)
__device__ uint4  g_l2h [N_TOTAL * U4_PER_ROW];   // layer-2 (half)

// ---------------------------------------------------------------------------
// Zero counters + scan ticket.
// ---------------------------------------------------------------------------
__global__ void zero_kernel() {
    int i = blockIdx.x * blockDim.x + threadIdx.x;
    if (i == 0) g_scan_done = 0;
    if (i < N_TOTAL) g_count[i] = 0;
}

// ---------------------------------------------------------------------------
// Histogram (no rank store) + fused fp32->fp16 conversion. The coalesced
// conversion streams through the atomic-latency stalls.
// ---------------------------------------------------------------------------
__global__ void __launch_bounds__(256) hist_kernel(const int* __restrict__ adj_row,
                                                   const float4* __restrict__ emb,
                                                   int n_edges) {
    int i = blockIdx.x * blockDim.x + threadIdx.x;
    int nthreads = gridDim.x * blockDim.x;

    int e = i * 8;
    if (e + 7 < n_edges) {
        #pragma unroll
        for (int g = 0; g < 2; g++) {
            int4 r = *(const int4*)(adj_row + e + g * 4);
            atomicAdd(&g_count[r.x], 1);
            atomicAdd(&g_count[r.y], 1);
            atomicAdd(&g_count[r.z], 1);
            atomicAdd(&g_count[r.w], 1);
        }
    } else if (e < n_edges) {
        for (int q = e; q < n_edges; q++)
            atomicAdd(&g_count[adj_row[q]], 1);
    }

    // fused conversion: node_emb fp32 -> fp16 (coalesced, independent)
    for (int c = i; c < N_TOTAL * U4_PER_ROW; c += nthreads) {
        float4 a = __ldg(emb + 2 * c);
        float4 b = __ldg(emb + 2 * c + 1);
        __half2 h0 = __floats2half2_rn(a.x, a.y);
        __half2 h1 = __floats2half2_rn(a.z, a.w);
        __half2 h2 = __floats2half2_rn(b.x, b.y);
        __half2 h3 = __floats2half2_rn(b.z, b.w);
        uint4 o;
        o.x = *reinterpret_cast<uint32_t*>(&h0);
        o.y = *reinterpret_cast<uint32_t*>(&h1);
        o.z = *reinterpret_cast<uint32_t*>(&h2);
        o.w = *reinterpret_cast<uint32_t*>(&h3);
        g_embh[c] = o;
    }
}

// ---------------------------------------------------------------------------
// Single-kernel scan: block-local exclusive scan; last block (atomic ticket)
// scans the 37 block totals, then ALL final offsets are materialized
// absolutely into BOTH g_offsets and g_cursor by a follow-up sweep here:
// we fold the bsum base in directly so consumers need no g_bsum lookup.
// ---------------------------------------------------------------------------
__global__ void scan_kernel() {
    __shared__ int wsum[32];
    __shared__ int s_last;
    __shared__ int w0tot;
    int tid  = threadIdx.x;
    int base = blockIdx.x * SCAN_CHUNK;
    int idx  = base + tid * 4;

    int a[4]; int sum = 0;
    #pragma unroll
    for (int k = 0; k < 4; k++) {
        int i = idx + k;
        a[k] = (i < N_TOTAL) ? g_count[i] : 0;
        sum += a[k];
    }
    int v = sum;
    #pragma unroll
    for (int off = 1; off < 32; off <<= 1) {
        int n = __shfl_up_sync(0xffffffffu, v, off);
        if ((tid & 31) >= off) v += n;
    }
    if ((tid & 31) == 31) wsum[tid >> 5] = v;
    __syncthreads();
    if (tid < 32) {
        int w = wsum[tid];
        #pragma unroll
        for (int off = 1; off < 32; off <<= 1) {
            int n = __shfl_up_sync(0xffffffffu, w, off);
            if (tid >= off) w += n;
        }
        wsum[tid] = w;
    }
    __syncthreads();
    int incl = v + ((tid >= 32) ? wsum[(tid >> 5) - 1] : 0);
    int run  = incl - sum;                 // block-local exclusive base
    #pragma unroll
    for (int k = 0; k < 4; k++) {
        int i = idx + k;
        if (i < N_TOTAL) g_offsets[i] = run;   // block-local for now
        run += a[k];
    }

    if (tid == 0) {
        g_bsum[blockIdx.x] = wsum[31];
        __threadfence();
        int ticket = atomicAdd(&g_scan_done, 1);
        s_last = (ticket == SCAN_NBLK - 1);
    }
    __syncthreads();

    if (s_last) {
        __threadfence();
        int bv = 0, x = 0;
        if (tid < 64) {
            bv = (tid < SCAN_NBLK) ? g_bsum[tid] : 0;
            x = bv;
            #pragma unroll
            for (int off = 1; off < 32; off <<= 1) {
                int n = __shfl_up_sync(0xffffffffu, x, off);
                if ((tid & 31) >= off) x += n;
            }
        }
        if (tid == 31) w0tot = x;
        __syncthreads();
        if (tid >= 32 && tid < 64) x += w0tot;
        if (tid < SCAN_NBLK) g_bsum[tid] = x - bv;
    }
}

// Materialize absolute offsets into g_offsets and g_cursor.
__global__ void finalize_kernel() {
    int i = blockIdx.x * blockDim.x + threadIdx.x;
    if (i >= N_TOTAL) return;
    int o = g_offsets[i] + __ldg(&g_bsum[i >> 12]);
    g_offsets[i] = o;
    g_cursor[i]  = o;
}

// ---------------------------------------------------------------------------
// fill: pure scatter; rank recomputed via cursor atomics (4 edges/thread).
// ---------------------------------------------------------------------------
__global__ void __launch_bounds__(256) fill_kernel(const int* __restrict__ adj_row,
                                                   const int* __restrict__ adj_col,
                                                   const float* __restrict__ adj_val,
                                                   int n_edges) {
    int i = blockIdx.x * blockDim.x + threadIdx.x;
    int e = i * 4;
    if (e + 3 < n_edges) {
        int4   r = *(const int4*)(adj_row + e);
        int4   c = *(const int4*)(adj_col + e);
        float4 v = *(const float4*)(adj_val + e);
        int p0 = atomicAdd(&g_cursor[r.x], 1);
        int p1 = atomicAdd(&g_cursor[r.y], 1);
        int p2 = atomicAdd(&g_cursor[r.z], 1);
        int p3 = atomicAdd(&g_cursor[r.w], 1);
        g_pedge[p0] = make_int2(c.x, __float_as_int(v.x));
        g_pedge[p1] = make_int2(c.y, __float_as_int(v.y));
        g_pedge[p2] = make_int2(c.z, __float_as_int(v.z));
        g_pedge[p3] = make_int2(c.w, __float_as_int(v.w));
    } else if (e < n_edges) {
        for (int q = e; q < n_edges; q++) {
            int p = atomicAdd(&g_cursor[adj_row[q]], 1);
            g_pedge[p] = make_int2(adj_col[q], __float_as_int(adj_val[q]));
        }
    }
}

// ---------------------------------------------------------------------------
// CSR SpMM in half: 8 lanes/row, lane owns 8 halves (uint4 = 16B).
// Software-pipelined 4-deep. fp32 accumulation, half output.
// ---------------------------------------------------------------------------
__device__ __forceinline__ void fma_h8(float2 acc[4], uint4 x, float v) {
    const __half2* h = reinterpret_cast<const __half2*>(&x);
    #pragma unroll
    for (int k = 0; k < 4; k++) {
        float2 f = __half22float2(h[k]);
        acc[k].x += v * f.x;
        acc[k].y += v * f.y;
    }
}

__global__ void __launch_bounds__(256) spmm_half_kernel(const uint4* __restrict__ in,
                                                        uint4* __restrict__ out) {
    int t    = blockIdx.x * blockDim.x + threadIdx.x;
    int r    = t >> 3;
    int lane = t & 7;
    if (r >= N_TOTAL) return;

    int beg = __ldg(&g_offsets[r]);
    int cnt = __ldg(&g_count[r]);

    float2 acc[4];
    #pragma unroll
    for (int k = 0; k < 4; k++) acc[k] = make_float2(0.f, 0.f);

    int j = 0;
    int2 ea0, ea1, ea2, ea3;
    if (j + 3 < cnt) {
        ea0 = __ldg(&g_pedge[beg]);
        ea1 = __ldg(&g_pedge[beg + 1]);
        ea2 = __ldg(&g_pedge[beg + 2]);
        ea3 = __ldg(&g_pedge[beg + 3]);
    }
    while (j + 3 < cnt) {
        uint4 x0 = __ldg(in + (long long)ea0.x * U4_PER_ROW + lane);
        uint4 x1 = __ldg(in + (long long)ea1.x * U4_PER_ROW + lane);
        uint4 x2 = __ldg(in + (long long)ea2.x * U4_PER_ROW + lane);
        uint4 x3 = __ldg(in + (long long)ea3.x * U4_PER_ROW + lane);
        int jn = j + 4;
        int2 eb0, eb1, eb2, eb3;
        bool more = (jn + 3 < cnt);
        if (more) {
            eb0 = __ldg(&g_pedge[beg + jn]);
            eb1 = __ldg(&g_pedge[beg + jn + 1]);
            eb2 = __ldg(&g_pedge[beg + jn + 2]);
            eb3 = __ldg(&g_pedge[beg + jn + 3]);
        }
        fma_h8(acc, x0, __int_as_float(ea0.y));
        fma_h8(acc, x1, __int_as_float(ea1.y));
        fma_h8(acc, x2, __int_as_float(ea2.y));
        fma_h8(acc, x3, __int_as_float(ea3.y));
        ea0 = eb0; ea1 = eb1; ea2 = eb2; ea3 = eb3;
        j = jn;
    }
    for (; j < cnt; j++) {
        int2 e0 = __ldg(&g_pedge[beg + j]);
        uint4 x0 = __ldg(in + (long long)e0.x * U4_PER_ROW + lane);
        fma_h8(acc, x0, __int_as_float(e0.y));
    }

    __half2 o0 = __floats2half2_rn(acc[0].x, acc[0].y);
    __half2 o1 = __floats2half2_rn(acc[1].x, acc[1].y);
    __half2 o2 = __floats2half2_rn(acc[2].x, acc[2].y);
    __half2 o3 = __floats2half2_rn(acc[3].x, acc[3].y);
    uint4 o;
    o.x = *reinterpret_cast<uint32_t*>(&o0);
    o.y = *reinterpret_cast<uint32_t*>(&o1);
    o.z = *reinterpret_cast<uint32_t*>(&o2);
    o.w = *reinterpret_cast<uint32_t*>(&o3);
    out[(long long)r * U4_PER_ROW + lane] = o;
}

// ---------------------------------------------------------------------------
// Fused layer-3 + accumulate + dot at the sampled rows.
// One warp per pair: lanes 0-15 user row, lanes 16-31 item row.
// ---------------------------------------------------------------------------
__global__ void final_kernel(const float4* __restrict__ emb,
                             const int* __restrict__ user_ids,
                             const int* __restrict__ item_ids,
                             float* __restrict__ out,
                             int n_pairs) {
    int t    = blockIdx.x * blockDim.x + threadIdx.x;
    int p    = t >> 5;
    int lane = t & 31;
    if (p >= n_pairs) return;

    int half_ = lane >> 4;                  // 0 = user, 1 = item
    int sl    = lane & 15;
    int row   = half_ ? (NUM_USERS + __ldg(item_ids + p)) : __ldg(user_ids + p);

    const uint2* l1u = reinterpret_cast<const uint2*>(g_l1h);
    const uint2* l2u = reinterpret_cast<const uint2*>(g_l2h);

    long long off = (long long)row * U2_PER_ROW + sl;
    float4 e4 = __ldg(emb + off);

    uint2 u1 = __ldg(l1u + off);
    uint2 u2 = __ldg(l2u + off);
    const __half2* h1 = reinterpret_cast<const __half2*>(&u1);
    const __half2* h2 = reinterpret_cast<const __half2*>(&u2);
    float2 a0 = __half22float2(h1[0]), a1 = __half22float2(h1[1]);
    float2 b0 = __half22float2(h2[0]), b1 = __half22float2(h2[1]);

    float4 acc = make_float4(e4.x + a0.x + b0.x,
                             e4.y + a0.y + b0.y,
                             e4.z + a1.x + b1.x,
                             e4.w + a1.y + b1.y);

    int beg = __ldg(&g_offsets[row]);
    int cnt = __ldg(&g_count[row]);
    float4 l3 = make_float4(0.f, 0.f, 0.f, 0.f);
    int j = 0;
    for (; j + 1 < cnt; j += 2) {
        int2 ed0 = __ldg(&g_pedge[beg + j]);
        int2 ed1 = __ldg(&g_pedge[beg + j + 1]);
        uint2 x0 = __ldg(l2u + (long long)ed0.x * U2_PER_ROW + sl);
        uint2 x1 = __ldg(l2u + (long long)ed1.x * U2_PER_ROW + sl);
        float v0 = __int_as_float(ed0.y), v1 = __int_as_float(ed1.y);
        const __half2* p0 = reinterpret_cast<const __half2*>(&x0);
        const __half2* p1 = reinterpret_cast<const __half2*>(&x1);
        float2 f00 = __half22float2(p0[0]), f01 = __half22float2(p0[1]);
        float2 f10 = __half22float2(p1[0]), f11 = __half22float2(p1[1]);
        l3.x += v0 * f00.x + v1 * f10.x;
        l3.y += v0 * f00.y + v1 * f10.y;
        l3.z += v0 * f01.x + v1 * f11.x;
        l3.w += v0 * f01.y + v1 * f11.y;
    }
    if (j < cnt) {
        int2 ed0 = __ldg(&g_pedge[beg + j]);
        uint2 x0 = __ldg(l2u + (long long)ed0.x * U2_PER_ROW + sl);
        float v0 = __int_as_float(ed0.y);
        const __half2* p0 = reinterpret_cast<const __half2*>(&x0);
        float2 f00 = __half22float2(p0[0]), f01 = __half22float2(p0[1]);
        l3.x += v0 * f00.x; l3.y += v0 * f00.y;
        l3.z += v0 * f01.x; l3.w += v0 * f01.y;
    }

    acc.x = (acc.x + l3.x) * 0.25f;
    acc.y = (acc.y + l3.y) * 0.25f;
    acc.z = (acc.z + l3.z) * 0.25f;
    acc.w = (acc.w + l3.w) * 0.25f;

    float4 oth;
    oth.x = __shfl_xor_sync(0xffffffffu, acc.x, 16);
    oth.y = __shfl_xor_sync(0xffffffffu, acc.y, 16);
    oth.z = __shfl_xor_sync(0xffffffffu, acc.z, 16);
    oth.w = __shfl_xor_sync(0xffffffffu, acc.w, 16);

    float partial = acc.x*oth.x + acc.y*oth.y + acc.z*oth.z + acc.w*oth.w;

    #pragma unroll
    for (int o = 8; o > 0; o >>= 1)
        partial += __shfl_down_sync(0xffffffffu, partial, o);

    if (lane == 0) out[p] = partial;
}

// ---------------------------------------------------------------------------
extern "C" void kernel_launch(void* const* d_in, const int* in_sizes, int n_in,
                              void* d_out, int out_size) {
    const float4* node_emb = (const float4*)d_in[0];
    const float*  adj_val  = (const float*)d_in[1];
    const int*    adj_row  = (const int*)d_in[2];
    const int*    adj_col  = (const int*)d_in[3];
    const int*    user_ids = (const int*)d_in[4];
    const int*    item_ids = (const int*)d_in[5];
    float*        out      = (float*)d_out;

    int n_edges = in_sizes[1];
    int n_pairs = out_size;

    uint4 *embh, *l1h, *l2h;
    cudaGetSymbolAddress((void**)&embh, g_embh);
    cudaGetSymbolAddress((void**)&l1h,  g_l1h);
    cudaGetSymbolAddress((void**)&l2h,  g_l2h);

    const int TB = 256;
    int node_blocks   = (N_TOTAL + TB - 1) / TB;
    int edge8_blocks  = ((n_edges + 7) / 8 + TB - 1) / TB;
    int edge4_blocks  = ((n_edges + 3) / 4 + TB - 1) / TB;
    int row_blocks    = (N_TOTAL * 8 + TB - 1) / TB;
    int pair_blocks   = (n_pairs * 32 + TB - 1) / TB;

    // --- CSR build (rank-free) + fused fp16 conversion ---
    zero_kernel<<<node_blocks, TB>>>();
    hist_kernel<<<edge8_blocks, TB>>>(adj_row, node_emb, n_edges);
    scan_kernel<<<SCAN_NBLK, SCAN_T>>>();
    finalize_kernel<<<node_blocks, TB>>>();
    fill_kernel<<<edge4_blocks, TB>>>(adj_row, adj_col, adj_val, n_edges);

    // --- 2 full propagation layers in half (8-lane pipelined) ---
    spmm_half_kernel<<<row_blocks, TB>>>(embh, l1h);    // l1
    spmm_half_kernel<<<row_blocks, TB>>>(l1h,  l2h);    // l2

    // --- fused l3 + acc + dot at the sampled rows only ---
    final_kernel<<<pair_blocks, TB>>>(node_emb, user_ids, item_ids, out, n_pairs);
}